// round 4
// baseline (speedup 1.0000x reference)
#include <cuda_runtime.h>
#include <math.h>

#define BB 512
#define SS 256
#define ID 12
#define HH 256
#define AA 9
#define G4 1024   // 4*HH

// -------- scratch (static device allocations; no runtime alloc) --------
static __device__ float g_seq[(size_t)BB * SS * HH];   // emb, then reused as y0
static __device__ float g_xg[(size_t)BB * SS * G4];    // precomputed input gates, cols gc = j*4+gate
static __device__ float g_hbuf[2][BB * HH];            // ping-pong hidden state
static __device__ float g_cbuf[BB * HH];               // cell state

__device__ __forceinline__ float sigm(float x) { return 1.f / (1.f + expf(-x)); }

// -------- zero h/c before each layer --------
__global__ void zero_hc_kernel() {
    int i = blockIdx.x * blockDim.x + threadIdx.x;
    if (i < BB * HH) { g_hbuf[0][i] = 0.f; g_cbuf[i] = 0.f; }
}

// -------- emb = relu(x @ W_emb^T + b_emb), x:[B*S,12], W:[256,12] --------
__global__ void emb_kernel(const float* __restrict__ x,
                           const float* __restrict__ W,
                           const float* __restrict__ bias) {
    __shared__ float ws[HH * ID];      // 12 KB
    __shared__ float xs[8][ID];
    int tid = threadIdx.x;
    for (int i = tid; i < HH * ID; i += 256) ws[i] = W[i];
    size_t row0 = (size_t)blockIdx.x * 8;
    if (tid < 8 * ID) xs[tid / ID][tid % ID] = x[row0 * ID + tid];
    __syncthreads();
    float b = bias[tid];
#pragma unroll
    for (int r = 0; r < 8; r++) {
        float acc = b;
#pragma unroll
        for (int i = 0; i < ID; i++) acc = fmaf(xs[r][i], ws[tid * ID + i], acc);
        g_seq[(row0 + r) * HH + tid] = fmaxf(acc, 0.f);
    }
}

// -------- xg[M,1024] = g_seq[M,256] @ w_ih^T  + (b_ih+b_hh), permuted cols --------
// output col gc -> weight row wr = (gc&3)*256 + (gc>>2)
// 128x128 tile, BK=16, 256 threads, 8x8 micro-tile (split 4+4)
__global__ void xg_gemm(const float* __restrict__ wih,
                        const float* __restrict__ bih,
                        const float* __restrict__ bhh) {
    __shared__ float a_s[16][132];
    __shared__ float b_s[16][132];
    int tid = threadIdx.x;
    int m0 = blockIdx.y * 128;
    int n0 = blockIdx.x * 128;
    int am = (tid >> 4) << 2;     // 0..60
    int an = (tid & 15) << 2;     // 0..60
    int lr = tid >> 2;            // 0..63
    int lk = (tid & 3) << 2;      // 0,4,8,12

    float acc[8][8];
#pragma unroll
    for (int i = 0; i < 8; i++)
#pragma unroll
        for (int j = 0; j < 8; j++) acc[i][j] = 0.f;

    for (int k0 = 0; k0 < HH; k0 += 16) {
        float4 v;
        v = *(const float4*)&g_seq[(size_t)(m0 + lr) * HH + k0 + lk];
        a_s[lk + 0][lr] = v.x; a_s[lk + 1][lr] = v.y; a_s[lk + 2][lr] = v.z; a_s[lk + 3][lr] = v.w;
        v = *(const float4*)&g_seq[(size_t)(m0 + lr + 64) * HH + k0 + lk];
        a_s[lk + 0][lr + 64] = v.x; a_s[lk + 1][lr + 64] = v.y; a_s[lk + 2][lr + 64] = v.z; a_s[lk + 3][lr + 64] = v.w;

        int gc = n0 + lr;
        int wr = ((gc & 3) << 8) | (gc >> 2);
        v = *(const float4*)&wih[(size_t)wr * HH + k0 + lk];
        b_s[lk + 0][lr] = v.x; b_s[lk + 1][lr] = v.y; b_s[lk + 2][lr] = v.z; b_s[lk + 3][lr] = v.w;
        gc = n0 + lr + 64;
        wr = ((gc & 3) << 8) | (gc >> 2);
        v = *(const float4*)&wih[(size_t)wr * HH + k0 + lk];
        b_s[lk + 0][lr + 64] = v.x; b_s[lk + 1][lr + 64] = v.y; b_s[lk + 2][lr + 64] = v.z; b_s[lk + 3][lr + 64] = v.w;
        __syncthreads();

#pragma unroll
        for (int k = 0; k < 16; k++) {
            float4 A0 = *(const float4*)&a_s[k][am];
            float4 A1 = *(const float4*)&a_s[k][am + 64];
            float4 B0 = *(const float4*)&b_s[k][an];
            float4 B1 = *(const float4*)&b_s[k][an + 64];
            float ar[8] = {A0.x, A0.y, A0.z, A0.w, A1.x, A1.y, A1.z, A1.w};
            float br[8] = {B0.x, B0.y, B0.z, B0.w, B1.x, B1.y, B1.z, B1.w};
#pragma unroll
            for (int i = 0; i < 8; i++)
#pragma unroll
                for (int j = 0; j < 8; j++)
                    acc[i][j] = fmaf(ar[i], br[j], acc[i][j]);
        }
        __syncthreads();
    }

    float bv[8];
#pragma unroll
    for (int jh = 0; jh < 2; jh++)
#pragma unroll
        for (int j = 0; j < 4; j++) {
            int gc = n0 + an + jh * 64 + j;
            int wr = ((gc & 3) << 8) | (gc >> 2);
            bv[jh * 4 + j] = bih[wr] + bhh[wr];
        }
#pragma unroll
    for (int ih = 0; ih < 2; ih++)
#pragma unroll
        for (int i = 0; i < 4; i++) {
            size_t m = (size_t)(m0 + am + ih * 64 + i);
#pragma unroll
            for (int jh = 0; jh < 2; jh++) {
                int gcb = n0 + an + jh * 64;
                float4 o;
                o.x = acc[ih * 4 + i][jh * 4 + 0] + bv[jh * 4 + 0];
                o.y = acc[ih * 4 + i][jh * 4 + 1] + bv[jh * 4 + 1];
                o.z = acc[ih * 4 + i][jh * 4 + 2] + bv[jh * 4 + 2];
                o.w = acc[ih * 4 + i][jh * 4 + 3] + bv[jh * 4 + 3];
                *(float4*)&g_xg[m * G4 + gcb] = o;
            }
        }
}

// -------- one LSTM time step: gates = xg[:,t,:] + h @ w_hh^T, cell update --------
// grid (8 j-blocks, 16 b-blocks), 256 threads. CTA tile: 32 batch x 32 units (128 gate cols)
// thread: 4 batch rows x (1 unit x 4 gates)
template <bool WRITE_Y>
__global__ void lstm_step(const float* __restrict__ whh, int t) {
    __shared__ float h_s[32][36];    // [k][b]
    __shared__ float w_s[32][132];   // [k][c], c = jlocal*4+gate
    int tid = threadIdx.x;
    int jb0 = blockIdx.x << 5;
    int bb0 = blockIdx.y << 5;
    const float* hprev = g_hbuf[t & 1];
    float* hnext = g_hbuf[(t & 1) ^ 1];

    int a4 = (tid >> 5) << 2;        // batch sub-tile base 0..28
    int jx = tid & 31;               // local unit
    int jx4 = jx << 2;

    int hr = tid >> 3;               // 0..31
    int hk = (tid & 7) << 2;         // 0..28
    int wc = tid & 127;              // 0..127
    int wk = (tid >> 7) << 4;        // 0 or 16
    int wrow = ((wc & 3) << 8) | (jb0 + (wc >> 2));

    float acc[4][4];
#pragma unroll
    for (int r = 0; r < 4; r++)
#pragma unroll
        for (int g = 0; g < 4; g++) acc[r][g] = 0.f;

    for (int k0 = 0; k0 < HH; k0 += 32) {
        float4 v = *(const float4*)&hprev[(size_t)(bb0 + hr) * HH + k0 + hk];
        h_s[hk + 0][hr] = v.x; h_s[hk + 1][hr] = v.y; h_s[hk + 2][hr] = v.z; h_s[hk + 3][hr] = v.w;
        const float* wp = whh + (size_t)wrow * HH + k0 + wk;
#pragma unroll
        for (int q = 0; q < 4; q++) {
            float4 w4 = *(const float4*)(wp + q * 4);
            w_s[wk + q * 4 + 0][wc] = w4.x; w_s[wk + q * 4 + 1][wc] = w4.y;
            w_s[wk + q * 4 + 2][wc] = w4.z; w_s[wk + q * 4 + 3][wc] = w4.w;
        }
        __syncthreads();
#pragma unroll
        for (int k = 0; k < 32; k++) {
            float4 hv = *(const float4*)&h_s[k][a4];
            float4 wv = *(const float4*)&w_s[k][jx4];
            float hrg[4] = {hv.x, hv.y, hv.z, hv.w};
            float wrg[4] = {wv.x, wv.y, wv.z, wv.w};
#pragma unroll
            for (int r = 0; r < 4; r++)
#pragma unroll
                for (int g = 0; g < 4; g++)
                    acc[r][g] = fmaf(hrg[r], wrg[g], acc[r][g]);
        }
        __syncthreads();
    }

    int j = jb0 + jx;
#pragma unroll
    for (int r = 0; r < 4; r++) {
        int b = bb0 + a4 + r;
        float4 xg = *(const float4*)&g_xg[((size_t)b * SS + t) * G4 + (size_t)j * 4];
        float iv = sigm(acc[r][0] + xg.x);
        float fv = sigm(acc[r][1] + xg.y);
        float gv = tanhf(acc[r][2] + xg.z);
        float ov = sigm(acc[r][3] + xg.w);
        size_t idx = (size_t)b * HH + j;
        float cn = fmaf(fv, g_cbuf[idx], iv * gv);
        float hn = ov * tanhf(cn);
        g_cbuf[idx] = cn;
        hnext[idx] = hn;
        if (WRITE_Y) g_seq[((size_t)b * SS + t) * HH + j] = hn;
    }
}

// -------- copy final h/c of a layer into d_out --------
__global__ void save_hc(float* __restrict__ oh, float* __restrict__ oc) {
    int i = blockIdx.x * blockDim.x + threadIdx.x;
    if (i < BB * HH) { oh[i] = g_hbuf[0][i]; oc[i] = g_cbuf[i]; }
}

// -------- head: layernorm(h1) -> relu(w1) -> w2 -> mask --------
__global__ void head_kernel(const float* __restrict__ mask,
                            const float* __restrict__ ln_g, const float* __restrict__ ln_b,
                            const float* __restrict__ w1, const float* __restrict__ b1,
                            const float* __restrict__ w2, const float* __restrict__ b2,
                            float* __restrict__ out_logits) {
    int b = blockIdx.x;
    int tid = threadIdx.x;
    __shared__ float sh[HH];
    __shared__ float r1[8], r2[8];
    __shared__ float stats[2];
    __shared__ float hdn[32];

    float v = g_hbuf[0][(size_t)b * HH + tid];
    float s1 = v, s2 = v * v;
#pragma unroll
    for (int off = 16; off > 0; off >>= 1) {
        s1 += __shfl_down_sync(0xffffffffu, s1, off);
        s2 += __shfl_down_sync(0xffffffffu, s2, off);
    }
    if ((tid & 31) == 0) { r1[tid >> 5] = s1; r2[tid >> 5] = s2; }
    __syncthreads();
    if (tid == 0) {
        float t1 = 0.f, t2 = 0.f;
        for (int i = 0; i < 8; i++) { t1 += r1[i]; t2 += r2[i]; }
        float mu = t1 * (1.f / HH);
        float var = t2 * (1.f / HH) - mu * mu;
        stats[0] = mu;
        stats[1] = rsqrtf(var + 1e-5f);
    }
    __syncthreads();
    sh[tid] = (v - stats[0]) * stats[1] * ln_g[tid] + ln_b[tid];
    __syncthreads();

    int u = tid >> 3, p = tid & 7;
    float part = 0.f;
#pragma unroll
    for (int k = p; k < HH; k += 8) part = fmaf(sh[k], w1[u * HH + k], part);
    part += __shfl_down_sync(0xffffffffu, part, 4);
    part += __shfl_down_sync(0xffffffffu, part, 2);
    part += __shfl_down_sync(0xffffffffu, part, 1);
    if (p == 0) hdn[u] = fmaxf(part + b1[u], 0.f);
    __syncthreads();

    if (tid < AA) {
        float acc = b2[tid];
#pragma unroll
        for (int k = 0; k < 32; k++) acc = fmaf(hdn[k], w2[tid * 32 + k], acc);
        acc += (1.f - mask[(size_t)b * AA + tid]) * -1e9f;
        out_logits[(size_t)b * AA + tid] = acc;
    }
}

extern "C" void kernel_launch(void* const* d_in, const int* in_sizes, int n_in,
                              void* d_out, int out_size) {
    (void)in_sizes; (void)n_in; (void)out_size;
    const float* x     = (const float*)d_in[0];
    const float* mask  = (const float*)d_in[1];
    const float* W_emb = (const float*)d_in[2];
    const float* b_emb = (const float*)d_in[3];
    const float* w_ih0 = (const float*)d_in[4];
    const float* w_hh0 = (const float*)d_in[5];
    const float* b_ih0 = (const float*)d_in[6];
    const float* b_hh0 = (const float*)d_in[7];
    const float* w_ih1 = (const float*)d_in[8];
    const float* w_hh1 = (const float*)d_in[9];
    const float* b_ih1 = (const float*)d_in[10];
    const float* b_hh1 = (const float*)d_in[11];
    const float* ln_g  = (const float*)d_in[12];
    const float* ln_b  = (const float*)d_in[13];
    const float* w1    = (const float*)d_in[14];
    const float* b1    = (const float*)d_in[15];
    const float* w2    = (const float*)d_in[16];
    const float* b2    = (const float*)d_in[17];

    float* out        = (float*)d_out;
    float* out_logits = out;                       // [512, 9]
    float* out_h0     = out + BB * AA;             // stack_h[0]
    float* out_h1     = out_h0 + BB * HH;          // stack_h[1]
    float* out_c0     = out_h1 + BB * HH;          // stack_c[0]
    float* out_c1     = out_c0 + BB * HH;          // stack_c[1]

    dim3 gemm_grid(G4 / 128, (BB * SS) / 128);     // (8, 1024)
    dim3 step_grid(HH / 32, BB / 32);              // (8, 16)

    // embedding
    emb_kernel<<<(BB * SS) / 8, 256>>>(x, W_emb, b_emb);

    // layer 0: precompute input gates, then recurrence
    xg_gemm<<<gemm_grid, 256>>>(w_ih0, b_ih0, b_hh0);
    zero_hc_kernel<<<(BB * HH) / 256, 256>>>();
    for (int t = 0; t < SS; t++)
        lstm_step<true><<<step_grid, 256>>>(w_hh0, t);
    save_hc<<<(BB * HH) / 256, 256>>>(out_h0, out_c0);

    // layer 1 (y0 now lives in g_seq)
    xg_gemm<<<gemm_grid, 256>>>(w_ih1, b_ih1, b_hh1);
    zero_hc_kernel<<<(BB * HH) / 256, 256>>>();
    for (int t = 0; t < SS; t++)
        lstm_step<false><<<step_grid, 256>>>(w_hh1, t);
    save_hc<<<(BB * HH) / 256, 256>>>(out_h1, out_c1);

    // head: last == final h1
    head_kernel<<<BB, 256>>>(mask, ln_g, ln_b, w1, b1, w2, b2, out_logits);
}

// round 5
// speedup vs baseline: 1.0013x; 1.0013x over previous
#include <cuda_runtime.h>
#include <math.h>

#define BB 512
#define SS 256
#define ID 12
#define HH 256
#define AA 9
#define G4 1024   // 4*HH

// -------- scratch (static device allocations; no runtime alloc) --------
static __device__ float g_seq[(size_t)BB * SS * HH];   // emb, then reused as y0
static __device__ float g_xg[(size_t)BB * SS * G4];    // precomputed input gates, cols gc = j*4+gate
static __device__ float g_hbuf[2][BB * HH];            // ping-pong hidden state
static __device__ float g_cbuf[BB * HH];               // cell state

__device__ __forceinline__ float sigm(float x) { return 1.f / (1.f + expf(-x)); }

// -------- zero h/c before each layer --------
__global__ void zero_hc_kernel() {
    int i = blockIdx.x * blockDim.x + threadIdx.x;
    if (i < BB * HH) { g_hbuf[0][i] = 0.f; g_cbuf[i] = 0.f; }
}

// -------- emb = relu(x @ W_emb^T + b_emb), x:[B*S,12], W:[256,12] --------
__global__ void emb_kernel(const float* __restrict__ x,
                           const float* __restrict__ W,
                           const float* __restrict__ bias) {
    __shared__ float ws[HH * ID];      // 12 KB
    __shared__ float xs[8][ID];
    int tid = threadIdx.x;
    for (int i = tid; i < HH * ID; i += 256) ws[i] = W[i];
    size_t row0 = (size_t)blockIdx.x * 8;
    if (tid < 8 * ID) xs[tid / ID][tid % ID] = x[row0 * ID + tid];
    __syncthreads();
    float b = bias[tid];
#pragma unroll
    for (int r = 0; r < 8; r++) {
        float acc = b;
#pragma unroll
        for (int i = 0; i < ID; i++) acc = fmaf(xs[r][i], ws[tid * ID + i], acc);
        g_seq[(row0 + r) * HH + tid] = fmaxf(acc, 0.f);
    }
}

// -------- xg[M,1024] = g_seq[M,256] @ w_ih^T  + (b_ih+b_hh), permuted cols --------
// output col gc -> weight row wr = (gc&3)*256 + (gc>>2)
// 128x128 tile, BK=16, 256 threads, 8x8 micro-tile (split 4+4)
__global__ void xg_gemm(const float* __restrict__ wih,
                        const float* __restrict__ bih,
                        const float* __restrict__ bhh) {
    __shared__ float a_s[16][132];
    __shared__ float b_s[16][132];
    int tid = threadIdx.x;
    int m0 = blockIdx.y * 128;
    int n0 = blockIdx.x * 128;
    int am = (tid >> 4) << 2;     // 0..60
    int an = (tid & 15) << 2;     // 0..60
    int lr = tid >> 2;            // 0..63
    int lk = (tid & 3) << 2;      // 0,4,8,12

    float acc[8][8];
#pragma unroll
    for (int i = 0; i < 8; i++)
#pragma unroll
        for (int j = 0; j < 8; j++) acc[i][j] = 0.f;

    for (int k0 = 0; k0 < HH; k0 += 16) {
        float4 v;
        v = *(const float4*)&g_seq[(size_t)(m0 + lr) * HH + k0 + lk];
        a_s[lk + 0][lr] = v.x; a_s[lk + 1][lr] = v.y; a_s[lk + 2][lr] = v.z; a_s[lk + 3][lr] = v.w;
        v = *(const float4*)&g_seq[(size_t)(m0 + lr + 64) * HH + k0 + lk];
        a_s[lk + 0][lr + 64] = v.x; a_s[lk + 1][lr + 64] = v.y; a_s[lk + 2][lr + 64] = v.z; a_s[lk + 3][lr + 64] = v.w;

        int gc = n0 + lr;
        int wr = ((gc & 3) << 8) | (gc >> 2);
        v = *(const float4*)&wih[(size_t)wr * HH + k0 + lk];
        b_s[lk + 0][lr] = v.x; b_s[lk + 1][lr] = v.y; b_s[lk + 2][lr] = v.z; b_s[lk + 3][lr] = v.w;
        gc = n0 + lr + 64;
        wr = ((gc & 3) << 8) | (gc >> 2);
        v = *(const float4*)&wih[(size_t)wr * HH + k0 + lk];
        b_s[lk + 0][lr + 64] = v.x; b_s[lk + 1][lr + 64] = v.y; b_s[lk + 2][lr + 64] = v.z; b_s[lk + 3][lr + 64] = v.w;
        __syncthreads();

#pragma unroll
        for (int k = 0; k < 16; k++) {
            float4 A0 = *(const float4*)&a_s[k][am];
            float4 A1 = *(const float4*)&a_s[k][am + 64];
            float4 B0 = *(const float4*)&b_s[k][an];
            float4 B1 = *(const float4*)&b_s[k][an + 64];
            float ar[8] = {A0.x, A0.y, A0.z, A0.w, A1.x, A1.y, A1.z, A1.w};
            float br[8] = {B0.x, B0.y, B0.z, B0.w, B1.x, B1.y, B1.z, B1.w};
#pragma unroll
            for (int i = 0; i < 8; i++)
#pragma unroll
                for (int j = 0; j < 8; j++)
                    acc[i][j] = fmaf(ar[i], br[j], acc[i][j]);
        }
        __syncthreads();
    }

    float bv[8];
#pragma unroll
    for (int jh = 0; jh < 2; jh++)
#pragma unroll
        for (int j = 0; j < 4; j++) {
            int gc = n0 + an + jh * 64 + j;
            int wr = ((gc & 3) << 8) | (gc >> 2);
            bv[jh * 4 + j] = bih[wr] + bhh[wr];
        }
#pragma unroll
    for (int ih = 0; ih < 2; ih++)
#pragma unroll
        for (int i = 0; i < 4; i++) {
            size_t m = (size_t)(m0 + am + ih * 64 + i);
#pragma unroll
            for (int jh = 0; jh < 2; jh++) {
                int gcb = n0 + an + jh * 64;
                float4 o;
                o.x = acc[ih * 4 + i][jh * 4 + 0] + bv[jh * 4 + 0];
                o.y = acc[ih * 4 + i][jh * 4 + 1] + bv[jh * 4 + 1];
                o.z = acc[ih * 4 + i][jh * 4 + 2] + bv[jh * 4 + 2];
                o.w = acc[ih * 4 + i][jh * 4 + 3] + bv[jh * 4 + 3];
                *(float4*)&g_xg[m * G4 + gcb] = o;
            }
        }
}

// -------- one LSTM time step: gates = xg[:,t,:] + h @ w_hh^T, cell update --------
// grid (8 j-blocks, 16 b-blocks), 256 threads. CTA tile: 32 batch x 32 units (128 gate cols)
// thread: 4 batch rows x (1 unit x 4 gates)
template <bool WRITE_Y>
__global__ void lstm_step(const float* __restrict__ whh, int t) {
    __shared__ float h_s[32][36];    // [k][b]
    __shared__ float w_s[32][132];   // [k][c], c = jlocal*4+gate
    int tid = threadIdx.x;
    int jb0 = blockIdx.x << 5;
    int bb0 = blockIdx.y << 5;
    const float* hprev = g_hbuf[t & 1];
    float* hnext = g_hbuf[(t & 1) ^ 1];

    int a4 = (tid >> 5) << 2;        // batch sub-tile base 0..28
    int jx = tid & 31;               // local unit
    int jx4 = jx << 2;

    int hr = tid >> 3;               // 0..31
    int hk = (tid & 7) << 2;         // 0..28
    int wc = tid & 127;              // 0..127
    int wk = (tid >> 7) << 4;        // 0 or 16
    int wrow = ((wc & 3) << 8) | (jb0 + (wc >> 2));

    float acc[4][4];
#pragma unroll
    for (int r = 0; r < 4; r++)
#pragma unroll
        for (int g = 0; g < 4; g++) acc[r][g] = 0.f;

    for (int k0 = 0; k0 < HH; k0 += 32) {
        float4 v = *(const float4*)&hprev[(size_t)(bb0 + hr) * HH + k0 + hk];
        h_s[hk + 0][hr] = v.x; h_s[hk + 1][hr] = v.y; h_s[hk + 2][hr] = v.z; h_s[hk + 3][hr] = v.w;
        const float* wp = whh + (size_t)wrow * HH + k0 + wk;
#pragma unroll
        for (int q = 0; q < 4; q++) {
            float4 w4 = *(const float4*)(wp + q * 4);
            w_s[wk + q * 4 + 0][wc] = w4.x; w_s[wk + q * 4 + 1][wc] = w4.y;
            w_s[wk + q * 4 + 2][wc] = w4.z; w_s[wk + q * 4 + 3][wc] = w4.w;
        }
        __syncthreads();
#pragma unroll
        for (int k = 0; k < 32; k++) {
            float4 hv = *(const float4*)&h_s[k][a4];
            float4 wv = *(const float4*)&w_s[k][jx4];
            float hrg[4] = {hv.x, hv.y, hv.z, hv.w};
            float wrg[4] = {wv.x, wv.y, wv.z, wv.w};
#pragma unroll
            for (int r = 0; r < 4; r++)
#pragma unroll
                for (int g = 0; g < 4; g++)
                    acc[r][g] = fmaf(hrg[r], wrg[g], acc[r][g]);
        }
        __syncthreads();
    }

    int j = jb0 + jx;
#pragma unroll
    for (int r = 0; r < 4; r++) {
        int b = bb0 + a4 + r;
        float4 xg = *(const float4*)&g_xg[((size_t)b * SS + t) * G4 + (size_t)j * 4];
        float iv = sigm(acc[r][0] + xg.x);
        float fv = sigm(acc[r][1] + xg.y);
        float gv = tanhf(acc[r][2] + xg.z);
        float ov = sigm(acc[r][3] + xg.w);
        size_t idx = (size_t)b * HH + j;
        float cn = fmaf(fv, g_cbuf[idx], iv * gv);
        float hn = ov * tanhf(cn);
        g_cbuf[idx] = cn;
        hnext[idx] = hn;
        if (WRITE_Y) g_seq[((size_t)b * SS + t) * HH + j] = hn;
    }
}

// -------- copy final h/c of a layer into d_out --------
__global__ void save_hc(float* __restrict__ oh, float* __restrict__ oc) {
    int i = blockIdx.x * blockDim.x + threadIdx.x;
    if (i < BB * HH) { oh[i] = g_hbuf[0][i]; oc[i] = g_cbuf[i]; }
}

// -------- head: layernorm(h1) -> relu(w1) -> w2 -> mask --------
__global__ void head_kernel(const float* __restrict__ mask,
                            const float* __restrict__ ln_g, const float* __restrict__ ln_b,
                            const float* __restrict__ w1, const float* __restrict__ b1,
                            const float* __restrict__ w2, const float* __restrict__ b2,
                            float* __restrict__ out_logits) {
    int b = blockIdx.x;
    int tid = threadIdx.x;
    __shared__ float sh[HH];
    __shared__ float r1[8], r2[8];
    __shared__ float stats[2];
    __shared__ float hdn[32];

    float v = g_hbuf[0][(size_t)b * HH + tid];
    float s1 = v, s2 = v * v;
#pragma unroll
    for (int off = 16; off > 0; off >>= 1) {
        s1 += __shfl_down_sync(0xffffffffu, s1, off);
        s2 += __shfl_down_sync(0xffffffffu, s2, off);
    }
    if ((tid & 31) == 0) { r1[tid >> 5] = s1; r2[tid >> 5] = s2; }
    __syncthreads();
    if (tid == 0) {
        float t1 = 0.f, t2 = 0.f;
        for (int i = 0; i < 8; i++) { t1 += r1[i]; t2 += r2[i]; }
        float mu = t1 * (1.f / HH);
        float var = t2 * (1.f / HH) - mu * mu;
        stats[0] = mu;
        stats[1] = rsqrtf(var + 1e-5f);
    }
    __syncthreads();
    sh[tid] = (v - stats[0]) * stats[1] * ln_g[tid] + ln_b[tid];
    __syncthreads();

    int u = tid >> 3, p = tid & 7;
    float part = 0.f;
#pragma unroll
    for (int k = p; k < HH; k += 8) part = fmaf(sh[k], w1[u * HH + k], part);
    part += __shfl_down_sync(0xffffffffu, part, 4);
    part += __shfl_down_sync(0xffffffffu, part, 2);
    part += __shfl_down_sync(0xffffffffu, part, 1);
    if (p == 0) hdn[u] = fmaxf(part + b1[u], 0.f);
    __syncthreads();

    if (tid < AA) {
        float acc = b2[tid];
#pragma unroll
        for (int k = 0; k < 32; k++) acc = fmaf(hdn[k], w2[tid * 32 + k], acc);
        acc += (1.f - mask[(size_t)b * AA + tid]) * -1e9f;
        out_logits[(size_t)b * AA + tid] = acc;
    }
}

extern "C" void kernel_launch(void* const* d_in, const int* in_sizes, int n_in,
                              void* d_out, int out_size) {
    (void)in_sizes; (void)n_in; (void)out_size;
    const float* x     = (const float*)d_in[0];
    const float* mask  = (const float*)d_in[1];
    const float* W_emb = (const float*)d_in[2];
    const float* b_emb = (const float*)d_in[3];
    const float* w_ih0 = (const float*)d_in[4];
    const float* w_hh0 = (const float*)d_in[5];
    const float* b_ih0 = (const float*)d_in[6];
    const float* b_hh0 = (const float*)d_in[7];
    const float* w_ih1 = (const float*)d_in[8];
    const float* w_hh1 = (const float*)d_in[9];
    const float* b_ih1 = (const float*)d_in[10];
    const float* b_hh1 = (const float*)d_in[11];
    const float* ln_g  = (const float*)d_in[12];
    const float* ln_b  = (const float*)d_in[13];
    const float* w1    = (const float*)d_in[14];
    const float* b1    = (const float*)d_in[15];
    const float* w2    = (const float*)d_in[16];
    const float* b2    = (const float*)d_in[17];

    float* out        = (float*)d_out;
    float* out_logits = out;                       // [512, 9]
    float* out_h0     = out + BB * AA;             // stack_h[0]
    float* out_h1     = out_h0 + BB * HH;          // stack_h[1]
    float* out_c0     = out_h1 + BB * HH;          // stack_c[0]
    float* out_c1     = out_c0 + BB * HH;          // stack_c[1]

    dim3 gemm_grid(G4 / 128, (BB * SS) / 128);     // (8, 1024)
    dim3 step_grid(HH / 32, BB / 32);              // (8, 16)

    // embedding
    emb_kernel<<<(BB * SS) / 8, 256>>>(x, W_emb, b_emb);

    // layer 0: precompute input gates, then recurrence
    xg_gemm<<<gemm_grid, 256>>>(w_ih0, b_ih0, b_hh0);
    zero_hc_kernel<<<(BB * HH) / 256, 256>>>();
    for (int t = 0; t < SS; t++)
        lstm_step<true><<<step_grid, 256>>>(w_hh0, t);
    save_hc<<<(BB * HH) / 256, 256>>>(out_h0, out_c0);

    // layer 1 (y0 now lives in g_seq)
    xg_gemm<<<gemm_grid, 256>>>(w_ih1, b_ih1, b_hh1);
    zero_hc_kernel<<<(BB * HH) / 256, 256>>>();
    for (int t = 0; t < SS; t++)
        lstm_step<false><<<step_grid, 256>>>(w_hh1, t);
    save_hc<<<(BB * HH) / 256, 256>>>(out_h1, out_c1);

    // head: last == final h1
    head_kernel<<<BB, 256>>>(mask, ln_g, ln_b, w1, b1, w2, b2, out_logits);
}